// round 1
// baseline (speedup 1.0000x reference)
#include <cuda_runtime.h>
#include <cstdint>
#include <math.h>

#define B 8
#define M 4096
#define E 1024
#define D 128
#define NCAT 64

#define SPLIT 8
#define M_PER (M / SPLIT)   // 512
#define E_TILE 128
#define MCHUNK 64

// ---------------- scratch (device globals; no allocations) ----------------
__device__ float d_part[(size_t)SPLIT * B * E * D];  // 32 MB partial agg
__device__ float d_agg[(size_t)B * E * D];           // 4 MB
__device__ float d_G[(size_t)B * E * D];             // 4 MB edge scores
__device__ float d_t[(size_t)B * E * D];             // 4 MB agg*attn
__device__ float d_WattT[D * D];
__device__ float d_v[D];
__device__ float d_cmax_p[B * 16 * D];
__device__ float d_csum_p[B * 16 * D];
__device__ float d_cmax[B * D];
__device__ float d_csum[B * D];
__device__ float d_a[B * E];
__device__ float d_amax[B];
__device__ float d_asum[B];
__device__ float d_spart[B * 16 * D];

// ---------------- K0: v = W_proj^T @ ec_att_w ; transpose W_att ----------------
__global__ void k0_prep(const float* __restrict__ W_att,
                        const float* __restrict__ W_proj,
                        const float* __restrict__ ec_att_w) {
    int t = threadIdx.x;  // 128
    float acc = 0.0f;
    for (int i = 0; i < D; i++) acc += ec_att_w[i] * W_proj[i * D + t];
    d_v[t] = acc;
    for (int i = 0; i < D; i++) d_WattT[t * D + i] = W_att[i * D + t];
}

// ---------------- K1: agg partials = inc^T @ nf (sparse bit-scan) ----------------
#define ACC_CASE(k) case k: acc[k].x += x.x; acc[k].y += x.y; acc[k].z += x.z; acc[k].w += x.w; break;

__global__ __launch_bounds__(256) void k1_agg(const float* __restrict__ nf,
                                              const float* __restrict__ inc) {
    __shared__ float nf_s[MCHUNK][D];                 // 32 KB
    __shared__ unsigned bits_s[MCHUNK][E_TILE / 32];  // 1 KB

    const int e0 = blockIdx.x * E_TILE;
    const int b  = blockIdx.y;
    const int sp = blockIdx.z;
    const int tid = threadIdx.x;
    const int w = tid >> 5;
    const int l = tid & 31;

    float4 acc[16];
#pragma unroll
    for (int j = 0; j < 16; j++) acc[j] = make_float4(0.f, 0.f, 0.f, 0.f);

    const float* nf_b  = nf  + (size_t)b * M * D;
    const float* inc_b = inc + (size_t)b * M * E;

    for (int c = 0; c < M_PER / MCHUNK; c++) {
        const int mb = sp * M_PER + c * MCHUNK;

        // stage nf chunk (contiguous 32KB)
        {
            const float4* src = (const float4*)(nf_b + (size_t)mb * D);
            float4* dst = (float4*)&nf_s[0][0];
#pragma unroll
            for (int i = 0; i < (MCHUNK * D / 4) / 256; i++)
                dst[tid + i * 256] = src[tid + i * 256];
        }
        // stage inc bits: warp w packs rows [w*8, w*8+8)
#pragma unroll
        for (int r = 0; r < 8; r++) {
            const int mi = w * 8 + r;
            const float* row = inc_b + (size_t)(mb + mi) * E + e0;
#pragma unroll
            for (int wd = 0; wd < 4; wd++) {
                float v = row[wd * 32 + l];
                unsigned bal = __ballot_sync(0xffffffffu, v != 0.0f);
                if (l == 0) bits_s[mi][wd] = bal;
            }
        }
        __syncthreads();

        const int shift = (w & 1) * 16;
        const int word  = w >> 1;
#pragma unroll 4
        for (int mm = 0; mm < MCHUNK; mm++) {
            unsigned bits = (bits_s[mm][word] >> shift) & 0xFFFFu;
            if (bits) {
                float4 x = *(const float4*)&nf_s[mm][l * 4];
                do {
                    int j = __ffs(bits) - 1;
                    bits &= bits - 1;
                    switch (j) {
                        ACC_CASE(0)  ACC_CASE(1)  ACC_CASE(2)  ACC_CASE(3)
                        ACC_CASE(4)  ACC_CASE(5)  ACC_CASE(6)  ACC_CASE(7)
                        ACC_CASE(8)  ACC_CASE(9)  ACC_CASE(10) ACC_CASE(11)
                        ACC_CASE(12) ACC_CASE(13) ACC_CASE(14) ACC_CASE(15)
                    }
                } while (bits);
            }
        }
        __syncthreads();
    }

    // write partials: warp w owns edges e0 + w*16 + j
    size_t base = (((size_t)sp * B + b) * E + (e0 + w * 16)) * D + l * 4;
#pragma unroll
    for (int j = 0; j < 16; j++)
        *(float4*)&d_part[base + (size_t)j * D] = acc[j];
}

// ---------------- K1c: agg = sum of partials ----------------
__global__ void k1c_reduce(void) {
    const size_t idx = (size_t)blockIdx.x * 256 + threadIdx.x;  // over B*E*D/4
    const float4* p = (const float4*)d_part;
    const size_t stride = (size_t)B * E * D / 4;
    float4 s = make_float4(0.f, 0.f, 0.f, 0.f);
#pragma unroll
    for (int k = 0; k < SPLIT; k++) {
        float4 v = p[(size_t)k * stride + idx];
        s.x += v.x; s.y += v.y; s.z += v.z; s.w += v.w;
    }
    ((float4*)d_agg)[idx] = s;
}

// ---------------- K2: G = agg @ W_att^T ----------------
__global__ __launch_bounds__(256) void k2_gemm(void) {
    __shared__ float agg_s[64][32];
    const int r0 = blockIdx.x * 64;
    const int tid = threadIdx.x;
    const int rr = (tid >> 5) * 8;   // 8 rows per thread
    const int c0 = (tid & 31) * 4;   // 4 cols per thread

    float4 acc[8];
#pragma unroll
    for (int k = 0; k < 8; k++) acc[k] = make_float4(0.f, 0.f, 0.f, 0.f);

    for (int kc = 0; kc < 4; kc++) {
#pragma unroll
        for (int i = tid; i < 2048; i += 256) {
            int r = i >> 5, j = i & 31;
            agg_s[r][j] = d_agg[(size_t)(r0 + r) * D + kc * 32 + j];
        }
        __syncthreads();
#pragma unroll
        for (int j = 0; j < 32; j++) {
            float4 wv = *(const float4*)&d_WattT[(size_t)(kc * 32 + j) * D + c0];
#pragma unroll
            for (int k = 0; k < 8; k++) {
                float a = agg_s[rr + k][j];
                acc[k].x += a * wv.x;
                acc[k].y += a * wv.y;
                acc[k].z += a * wv.z;
                acc[k].w += a * wv.w;
            }
        }
        __syncthreads();
    }
#pragma unroll
    for (int k = 0; k < 8; k++)
        *(float4*)&d_G[(size_t)(r0 + rr + k) * D + c0] = acc[k];
}

// ---------------- K3: softmax stats over edge dim, per (b,d) ----------------
__global__ void k3a(void) {
    const int ch = blockIdx.x, b = blockIdx.y;
    const int d = threadIdx.x;  // 128
    const float* Gp = d_G + ((size_t)b * E + ch * 64) * D + d;
    float mx = -INFINITY, sum = 0.0f;
    for (int e = 0; e < 64; e++) {
        float v = Gp[(size_t)e * D];
        if (v > mx) { sum = sum * __expf(mx - v) + 1.0f; mx = v; }
        else        { sum += __expf(v - mx); }
    }
    d_cmax_p[(b * 16 + ch) * D + d] = mx;
    d_csum_p[(b * 16 + ch) * D + d] = sum;
}

__global__ void k3b(void) {
    const int b = blockIdx.x, d = threadIdx.x;
    float mx = -INFINITY;
    for (int ch = 0; ch < 16; ch++) mx = fmaxf(mx, d_cmax_p[(b * 16 + ch) * D + d]);
    float sum = 0.0f;
    for (int ch = 0; ch < 16; ch++)
        sum += d_csum_p[(b * 16 + ch) * D + d] * __expf(d_cmax_p[(b * 16 + ch) * D + d] - mx);
    d_cmax[b * D + d] = mx;
    d_csum[b * D + d] = sum;
}

// ---------------- K4: t = agg*attn ; a[b,e] = t . v ----------------
__global__ void k4(void) {
    __shared__ float red[4];
    const int r = blockIdx.x;     // B*E
    const int b = r >> 10;        // E = 1024
    const int d = threadIdx.x;    // 128
    float g = d_G[(size_t)r * D + d];
    float attn = __expf(g - d_cmax[b * D + d]) / d_csum[b * D + d];
    float t = d_agg[(size_t)r * D + d] * attn;
    d_t[(size_t)r * D + d] = t;
    float p = t * d_v[d];
#pragma unroll
    for (int o = 16; o; o >>= 1) p += __shfl_xor_sync(0xffffffffu, p, o);
    if ((d & 31) == 0) red[d >> 5] = p;
    __syncthreads();
    if (d == 0) d_a[r] = red[0] + red[1] + red[2] + red[3];
}

// ---------------- K5pre: softmax stats of a over edges ----------------
__global__ void k5pre(void) {
    __shared__ float sm[256];
    const int b = blockIdx.x, t = threadIdx.x;  // 256 threads
    float mx = -INFINITY;
    for (int e = t; e < E; e += 256) mx = fmaxf(mx, d_a[b * E + e]);
    sm[t] = mx; __syncthreads();
    for (int s = 128; s; s >>= 1) { if (t < s) sm[t] = fmaxf(sm[t], sm[t + s]); __syncthreads(); }
    float gmx = sm[0]; __syncthreads();
    float sum = 0.0f;
    for (int e = t; e < E; e += 256) sum += __expf(d_a[b * E + e] - gmx);
    sm[t] = sum; __syncthreads();
    for (int s = 128; s; s >>= 1) { if (t < s) sm[t] += sm[t + s]; __syncthreads(); }
    if (t == 0) { d_amax[b] = gmx; d_asum[b] = sm[0]; }
}

// ---------------- K5a: partial s[b,d] = sum_e exp(a-amax) * t ----------------
__global__ void k5a(void) {
    __shared__ float ws[64];
    const int ch = blockIdx.x, b = blockIdx.y;
    const int d = threadIdx.x;  // 128
    if (d < 64) ws[d] = __expf(d_a[b * E + ch * 64 + d] - d_amax[b]);
    __syncthreads();
    const float* tp = d_t + ((size_t)b * E + ch * 64) * D + d;
    float acc = 0.0f;
#pragma unroll 4
    for (int e = 0; e < 64; e++) acc += ws[e] * tp[(size_t)e * D];
    d_spart[(b * 16 + ch) * D + d] = acc;
}

// ---------------- K6: final projections -> logits ----------------
__global__ void k6(const float* __restrict__ W_proj,
                   const float* __restrict__ ec_proj_w,
                   const float* __restrict__ ec_proj_b,
                   const float* __restrict__ fc_w,
                   const float* __restrict__ fc_b,
                   float* __restrict__ out) {
    __shared__ float sf[D], ef[D], ov[D];
    const int b = blockIdx.x, t = threadIdx.x;  // 128
    float s = 0.0f;
    for (int ch = 0; ch < 16; ch++) s += d_spart[(b * 16 + ch) * D + t];
    sf[t] = s / d_asum[b];
    __syncthreads();
    float acc = 0.0f;
    for (int j = 0; j < D; j++) acc += sf[j] * W_proj[t * D + j];
    ef[t] = acc;
    __syncthreads();
    float acc2 = 0.0f;
    for (int j = 0; j < D; j++) acc2 += ef[j] * ec_proj_w[t * D + j];
    ov[t] = acc2 + ec_proj_b[t];
    __syncthreads();
    if (t < NCAT) {
        float acc3 = 0.0f;
        for (int j = 0; j < D; j++) acc3 += ov[j] * fc_w[t * D + j];
        out[b * NCAT + t] = acc3 + fc_b[t];
    }
}

// ---------------- launch ----------------
extern "C" void kernel_launch(void* const* d_in, const int* in_sizes, int n_in,
                              void* d_out, int out_size) {
    const float* nf        = (const float*)d_in[0];
    const float* inc       = (const float*)d_in[1];
    const float* W_att     = (const float*)d_in[2];
    const float* W_proj    = (const float*)d_in[3];
    const float* ec_att_w  = (const float*)d_in[4];
    const float* ec_proj_w = (const float*)d_in[5];
    const float* ec_proj_b = (const float*)d_in[6];
    const float* fc_w      = (const float*)d_in[7];
    const float* fc_b      = (const float*)d_in[8];
    float* out = (float*)d_out;

    k0_prep<<<1, 128>>>(W_att, W_proj, ec_att_w);
    k1_agg<<<dim3(E / E_TILE, B, SPLIT), 256>>>(nf, inc);
    k1c_reduce<<<(B * E * D / 4) / 256, 256>>>();
    k2_gemm<<<(B * E) / 64, 256>>>();
    k3a<<<dim3(16, B), 128>>>();
    k3b<<<B, 128>>>();
    k4<<<B * E, 128>>>();
    k5pre<<<B, 256>>>();
    k5a<<<dim3(16, B), 128>>>();
    k6<<<B, 128>>>(W_proj, ec_proj_w, ec_proj_b, fc_w, fc_b, out);
}